// round 11
// baseline (speedup 1.0000x reference)
#include <cuda_runtime.h>
#include <cuda_bf16.h>
#include <cstdint>

#define N_RAYS 32768
#define M_G    1024
#define NTILES (M_G / 8)       // 128 n-tiles of 8 gaussians
#define WARPS  8
#define RAYS_PER_WARP 16
#define RAYS_PER_BLOCK (WARPS * RAYS_PER_WARP)   // 128

typedef unsigned int u32;
typedef unsigned long long ull;

__device__ __forceinline__ u32 pack_bf16x2(float a, float b) {
    __nv_bfloat16 x = __float2bfloat16(a), y = __float2bfloat16(b);
    return (u32)__bfloat16_as_ushort(x) | ((u32)__bfloat16_as_ushort(y) << 16);
}

// SMEM layout: B-frag table (64KB) + permuted labels (4KB) + A staging (12.8KB)
#define SM_TBL   0
#define SM_LAB   (NTILES * 2 * 32 * 8)               // 65536
#define SM_STAGE (SM_LAB + M_G * 4)                  // 69632
#define STAGE_W  25
#define SM_TOTAL (SM_STAGE + RAYS_PER_BLOCK * STAGE_W * 4)  // 82432

extern __shared__ unsigned char smem_raw[];

__device__ __forceinline__ void mma16816(float& c0, float& c1, float& c2, float& c3,
                                         u32 a0, u32 a1, u32 a2, u32 a3,
                                         u32 b0, u32 b1) {
    asm volatile(
        "mma.sync.aligned.m16n8k16.row.col.f32.bf16.bf16.f32 "
        "{%0,%1,%2,%3}, {%4,%5,%6,%7}, {%8,%9}, {%0,%1,%2,%3};"
        : "+f"(c0), "+f"(c1), "+f"(c2), "+f"(c3)
        : "r"(a0), "r"(a1), "r"(a2), "r"(a3), "r"(b0), "r"(b1));
}

// ---------------------------------------------------------------------------
// Single fused kernel: phase 0 builds the coefficient table in SMEM (each
// thread inverts 4 covariances: fp32 GJ + one Newton step, folds -0.5*log2(e)
// and mean, splits bf16 hi/lo, writes m16n8k16-layout fragments + permuted
// labels). Phase 1 = R8 main loop: 8 warps x 16 rays, 64 rounds of 2
// interleaved n-tiles (6 HMMAs, 8 ex2, 8 FMA per round).
// ---------------------------------------------------------------------------
__global__ void __launch_bounds__(256, 2)
decoder_kernel(const float* __restrict__ origins,
               const float* __restrict__ dirs,
               const float* __restrict__ means,
               const float* __restrict__ covs,
               const float* __restrict__ labels,
               float* __restrict__ out) {
    const int tid  = threadIdx.x;
    const int wid  = tid >> 5;
    const int lane = tid & 31;
    const int gid  = lane >> 2;   // row group 0..7
    const int tig  = lane & 3;    // thread-in-group

    ull*   s_tbl  = reinterpret_cast<ull*>(smem_raw + SM_TBL);
    float* s_lab  = reinterpret_cast<float*>(smem_raw + SM_LAB);

    // ================= phase 0: build table in SMEM =================
    #pragma unroll 1
    for (int i = 0; i < M_G / 256; i++) {
        const int m = i * 256 + tid;

        float S[4][4], a[4][8];
        #pragma unroll
        for (int r = 0; r < 4; r++)
            #pragma unroll
            for (int c = 0; c < 4; c++) {
                S[r][c] = covs[m * 16 + r * 4 + c];
                a[r][c] = S[r][c];
            }
        #pragma unroll
        for (int r = 0; r < 4; r++)
            #pragma unroll
            for (int c = 0; c < 4; c++) a[r][4 + c] = (r == c) ? 1.0f : 0.0f;
        #pragma unroll
        for (int c = 0; c < 4; c++) {
            float inv = __frcp_rn(a[c][c]);
            #pragma unroll
            for (int j = 0; j < 8; j++) a[c][j] *= inv;
            #pragma unroll
            for (int r = 0; r < 4; r++) {
                if (r == c) continue;
                float f = a[r][c];
                #pragma unroll
                for (int j = 0; j < 8; j++) a[r][j] = fmaf(-f, a[c][j], a[r][j]);
            }
        }
        float X[4][4], T[4][4], Xr[4][4];
        #pragma unroll
        for (int r = 0; r < 4; r++)
            #pragma unroll
            for (int c = 0; c < 4; c++) X[r][c] = a[r][4 + c];
        #pragma unroll
        for (int r = 0; r < 4; r++)
            #pragma unroll
            for (int c = 0; c < 4; c++) {
                float s = (r == c) ? 2.0f : 0.0f;
                #pragma unroll
                for (int k = 0; k < 4; k++) s = fmaf(-S[r][k], X[k][c], s);
                T[r][c] = s;
            }
        #pragma unroll
        for (int r = 0; r < 4; r++)
            #pragma unroll
            for (int c = 0; c < 4; c++) {
                float s = 0.0f;
                #pragma unroll
                for (int k = 0; k < 4; k++) s = fmaf(X[r][k], T[k][c], s);
                Xr[r][c] = s;
            }
        const float kk = -0.5f * 1.4426950408889634f;   // -0.5*log2(e)
        float C[4][4];
        #pragma unroll
        for (int r = 0; r < 4; r++)
            #pragma unroll
            for (int c = 0; c < 4; c++) C[r][c] = kk * Xr[r][c];
        float mu[4];
        #pragma unroll
        for (int r = 0; r < 4; r++) mu[r] = means[m * 4 + r];

        float w[16];
        w[0] = C[0][0]; w[1] = C[1][1]; w[2] = C[2][2]; w[3] = C[3][3];
        w[4] = 2.0f * C[0][1]; w[5] = 2.0f * C[0][2]; w[6] = 2.0f * C[0][3];
        w[7] = 2.0f * C[1][2]; w[8] = 2.0f * C[1][3]; w[9] = 2.0f * C[2][3];
        #pragma unroll
        for (int r = 0; r < 4; r++) {
            float s = 0.0f;
            #pragma unroll
            for (int c = 0; c < 4; c++) s = fmaf(C[r][c], mu[c], s);
            w[10 + r] = -2.0f * s;
        }
        float q = 0.0f;
        #pragma unroll
        for (int r = 0; r < 4; r++) {
            float s = 0.0f;
            #pragma unroll
            for (int c = 0; c < 4; c++) s = fmaf(C[r][c], mu[c], s);
            q = fmaf(mu[r], s, q);
        }
        w[14] = q;
        w[15] = 0.0f;

        float hi[16], lo[16];
        #pragma unroll
        for (int k = 0; k < 16; k++) {
            __nv_bfloat16 h = __float2bfloat16(w[k]);
            hi[k] = __bfloat162float(h);
            lo[k] = w[k] - hi[k];
        }

        const int t = m >> 3, j = m & 7;
        #pragma unroll
        for (int tg = 0; tg < 4; tg++) {
            u32 h0 = pack_bf16x2(hi[2 * tg],     hi[2 * tg + 1]);
            u32 h1 = pack_bf16x2(hi[2 * tg + 8], hi[2 * tg + 9]);
            u32 l0 = pack_bf16x2(lo[2 * tg],     lo[2 * tg + 1]);
            u32 l1 = pack_bf16x2(lo[2 * tg + 8], lo[2 * tg + 9]);
            const int ln = 4 * j + tg;
            s_tbl[(t * 2 + 0) * 32 + ln] = (ull)h0 | ((ull)h1 << 32);  // hi
            s_tbl[(t * 2 + 1) * 32 + ln] = (ull)l0 | ((ull)l1 << 32);  // lo
        }
        // permuted label: round r = t>>1, odd = t&1, tg = j>>1, p = j&1
        {
            const int r = t >> 1, odd = t & 1, tg = j >> 1, p = j & 1;
            s_lab[r * 16 + tg * 4 + odd * 2 + p] = labels[m];
        }
    }

    // ---- A staging (overlaps with other warps' phase-0 math) ----
    u32* stage = reinterpret_cast<u32*>(smem_raw + SM_STAGE) +
                 wid * RAYS_PER_WARP * STAGE_W;
    const int ray_base = blockIdx.x * RAYS_PER_BLOCK + wid * RAYS_PER_WARP;
    if (lane < 16) {
        const int n = ray_base + lane;
        const float2 o = reinterpret_cast<const float2*>(origins)[n];
        const float2 d = reinterpret_cast<const float2*>(dirs)[n];
        const float p0 = o.x, p1 = o.y, p2 = d.x, p3 = d.y;
        float phi[16];
        phi[0] = p0 * p0; phi[1] = p1 * p1; phi[2] = p2 * p2; phi[3] = p3 * p3;
        phi[4] = p0 * p1; phi[5] = p0 * p2; phi[6] = p0 * p3;
        phi[7] = p1 * p2; phi[8] = p1 * p3; phi[9] = p2 * p3;
        phi[10] = p0; phi[11] = p1; phi[12] = p2; phi[13] = p3;
        phi[14] = 1.0f; phi[15] = 0.0f;
        float hi[16], lo[16];
        #pragma unroll
        for (int k = 0; k < 16; k++) {
            __nv_bfloat16 h = __float2bfloat16(phi[k]);
            hi[k] = __bfloat162float(h);
            lo[k] = phi[k] - hi[k];
        }
        u32* row = stage + lane * STAGE_W;
        #pragma unroll
        for (int wd = 0; wd < 8; wd++) {
            row[wd]      = pack_bf16x2(hi[2 * wd], hi[2 * wd + 1]);  // hi
            row[8 + wd]  = pack_bf16x2(lo[2 * wd], lo[2 * wd + 1]);  // lo
            row[16 + wd] = row[wd];                                   // hi again
        }
    }
    __syncthreads();

    // ================= phase 1: GEMM + exp epilogue =================
    u32 afr[3][4];
    #pragma unroll
    for (int s = 0; s < 3; s++) {
        afr[s][0] = stage[gid * STAGE_W       + 8 * s + tig];
        afr[s][1] = stage[(gid + 8) * STAGE_W + 8 * s + tig];
        afr[s][2] = stage[gid * STAGE_W       + 8 * s + tig + 4];
        afr[s][3] = stage[(gid + 8) * STAGE_W + 8 * s + tig + 4];
    }

    const float4* lab4 = reinterpret_cast<const float4*>(smem_raw + SM_LAB);

    float acc0 = 0.0f, acc1 = 0.0f, acc2 = 0.0f, acc3 = 0.0f;

    #pragma unroll 2
    for (int r = 0; r < NTILES / 2; r++) {
        const ull* bt = s_tbl + r * 128 + lane;
        const ull hhx = bt[0];           // tile 2r   hi
        const ull llx = bt[32];          // tile 2r   lo
        const ull hhy = bt[64];          // tile 2r+1 hi
        const ull lly = bt[96];          // tile 2r+1 lo
        const float4 L = lab4[r * 4 + tig];

        float xA0 = 0.f, xA1 = 0.f, xA2 = 0.f, xA3 = 0.f;
        float xB0 = 0.f, xB1 = 0.f, xB2 = 0.f, xB3 = 0.f;
        mma16816(xA0, xA1, xA2, xA3, afr[0][0], afr[0][1], afr[0][2], afr[0][3],
                 (u32)hhx, (u32)(hhx >> 32));
        mma16816(xB0, xB1, xB2, xB3, afr[1][0], afr[1][1], afr[1][2], afr[1][3],
                 (u32)hhx, (u32)(hhx >> 32));
        mma16816(xB0, xB1, xB2, xB3, afr[2][0], afr[2][1], afr[2][2], afr[2][3],
                 (u32)llx, (u32)(llx >> 32));

        float yA0 = 0.f, yA1 = 0.f, yA2 = 0.f, yA3 = 0.f;
        float yB0 = 0.f, yB1 = 0.f, yB2 = 0.f, yB3 = 0.f;
        mma16816(yA0, yA1, yA2, yA3, afr[0][0], afr[0][1], afr[0][2], afr[0][3],
                 (u32)hhy, (u32)(hhy >> 32));
        mma16816(yB0, yB1, yB2, yB3, afr[1][0], afr[1][1], afr[1][2], afr[1][3],
                 (u32)hhy, (u32)(hhy >> 32));
        mma16816(yB0, yB1, yB2, yB3, afr[2][0], afr[2][1], afr[2][2], afr[2][3],
                 (u32)lly, (u32)(lly >> 32));

        float e;
        asm("ex2.approx.ftz.f32 %0, %1;" : "=f"(e) : "f"(xA0 + xB0));
        acc0 = fmaf(L.x, e, acc0);
        asm("ex2.approx.ftz.f32 %0, %1;" : "=f"(e) : "f"(xA1 + xB1));
        acc1 = fmaf(L.y, e, acc1);
        asm("ex2.approx.ftz.f32 %0, %1;" : "=f"(e) : "f"(xA2 + xB2));
        acc2 = fmaf(L.x, e, acc2);
        asm("ex2.approx.ftz.f32 %0, %1;" : "=f"(e) : "f"(xA3 + xB3));
        acc3 = fmaf(L.y, e, acc3);
        asm("ex2.approx.ftz.f32 %0, %1;" : "=f"(e) : "f"(yA0 + yB0));
        acc0 = fmaf(L.z, e, acc0);
        asm("ex2.approx.ftz.f32 %0, %1;" : "=f"(e) : "f"(yA1 + yB1));
        acc1 = fmaf(L.w, e, acc1);
        asm("ex2.approx.ftz.f32 %0, %1;" : "=f"(e) : "f"(yA2 + yB2));
        acc2 = fmaf(L.z, e, acc2);
        asm("ex2.approx.ftz.f32 %0, %1;" : "=f"(e) : "f"(yA3 + yB3));
        acc3 = fmaf(L.w, e, acc3);
    }

    float accLo = acc0 + acc1;   // ray gid
    float accHi = acc2 + acc3;   // ray gid+8

    #pragma unroll
    for (int d = 1; d < 4; d <<= 1) {
        accLo += __shfl_xor_sync(0xffffffffu, accLo, d);
        accHi += __shfl_xor_sync(0xffffffffu, accHi, d);
    }

    if (tig == 0) {
        const float zL = -accLo * 1.4426950408889634f;
        const float zH = -accHi * 1.4426950408889634f;
        float eL, eH, pL, pH;
        asm("ex2.approx.ftz.f32 %0, %1;" : "=f"(eL) : "f"(zL));
        asm("ex2.approx.ftz.f32 %0, %1;" : "=f"(eH) : "f"(zH));
        asm("rcp.approx.ftz.f32 %0, %1;" : "=f"(pL) : "f"(1.0f + eL));
        asm("rcp.approx.ftz.f32 %0, %1;" : "=f"(pH) : "f"(1.0f + eH));
        out[ray_base + gid]     = pL;
        out[ray_base + gid + 8] = pH;
    }
}

// ---------------------------------------------------------------------------
extern "C" void kernel_launch(void* const* d_in, const int* in_sizes, int n_in,
                              void* d_out, int out_size) {
    const float* origins    = (const float*)d_in[0];
    const float* directions = (const float*)d_in[1];
    const float* means      = (const float*)d_in[2];
    const float* covs       = (const float*)d_in[3];
    const float* labels     = (const float*)d_in[4];
    float* out = (float*)d_out;

    cudaFuncSetAttribute(decoder_kernel,
                         cudaFuncAttributeMaxDynamicSharedMemorySize, SM_TOTAL);
    decoder_kernel<<<N_RAYS / RAYS_PER_BLOCK, 256, SM_TOTAL>>>(
        origins, directions, means, covs, labels, out);
}

// round 12
// speedup vs baseline: 1.0094x; 1.0094x over previous
#include <cuda_runtime.h>
#include <cuda_bf16.h>
#include <cstdint>

#define N_RAYS 32768
#define M_G    1024
#define NTILES (M_G / 8)       // 128 n-tiles of 8 gaussians
#define WARPS  8
#define RAYS_PER_WARP 16
#define RAYS_PER_BLOCK (WARPS * RAYS_PER_WARP)   // 128

typedef unsigned int u32;
typedef unsigned long long ull;

__device__ __forceinline__ u32 pack_bf16x2(float a, float b) {
    __nv_bfloat16 x = __float2bfloat16(a), y = __float2bfloat16(b);
    return (u32)__bfloat16_as_ushort(x) | ((u32)__bfloat16_as_ushort(y) << 16);
}

// SMEM layout: B-frag table (64KB) + permuted labels (4KB) + A staging (12.8KB)
#define SM_TBL   0
#define SM_LAB   (NTILES * 2 * 32 * 8)               // 65536
#define SM_STAGE (SM_LAB + M_G * 4)                  // 69632
#define STAGE_W  25
#define SM_TOTAL (SM_STAGE + RAYS_PER_BLOCK * STAGE_W * 4)  // 82432

extern __shared__ unsigned char smem_raw[];

__device__ __forceinline__ void mma16816(float& c0, float& c1, float& c2, float& c3,
                                         u32 a0, u32 a1, u32 a2, u32 a3,
                                         u32 b0, u32 b1) {
    asm volatile(
        "mma.sync.aligned.m16n8k16.row.col.f32.bf16.bf16.f32 "
        "{%0,%1,%2,%3}, {%4,%5,%6,%7}, {%8,%9}, {%0,%1,%2,%3};"
        : "+f"(c0), "+f"(c1), "+f"(c2), "+f"(c3)
        : "r"(a0), "r"(a1), "r"(a2), "r"(a3), "r"(b0), "r"(b1));
}

// ---------------------------------------------------------------------------
// Single fused kernel: phase 0 builds the coefficient table in SMEM (each
// thread inverts 4 covariances: fp32 GJ + one Newton step, folds -0.5*log2(e)
// and mean, splits bf16 hi/lo, writes m16n8k16-layout fragments + permuted
// labels). Phase 1 = R8 main loop: 8 warps x 16 rays, 64 rounds of 2
// interleaved n-tiles (6 HMMAs, 8 ex2, 8 FMA per round).
// ---------------------------------------------------------------------------
__global__ void __launch_bounds__(256, 2)
decoder_kernel(const float* __restrict__ origins,
               const float* __restrict__ dirs,
               const float* __restrict__ means,
               const float* __restrict__ covs,
               const float* __restrict__ labels,
               float* __restrict__ out) {
    const int tid  = threadIdx.x;
    const int wid  = tid >> 5;
    const int lane = tid & 31;
    const int gid  = lane >> 2;   // row group 0..7
    const int tig  = lane & 3;    // thread-in-group

    ull*   s_tbl  = reinterpret_cast<ull*>(smem_raw + SM_TBL);
    float* s_lab  = reinterpret_cast<float*>(smem_raw + SM_LAB);

    // ================= phase 0: build table in SMEM =================
    #pragma unroll 1
    for (int i = 0; i < M_G / 256; i++) {
        const int m = i * 256 + tid;

        float S[4][4], a[4][8];
        #pragma unroll
        for (int r = 0; r < 4; r++)
            #pragma unroll
            for (int c = 0; c < 4; c++) {
                S[r][c] = covs[m * 16 + r * 4 + c];
                a[r][c] = S[r][c];
            }
        #pragma unroll
        for (int r = 0; r < 4; r++)
            #pragma unroll
            for (int c = 0; c < 4; c++) a[r][4 + c] = (r == c) ? 1.0f : 0.0f;
        #pragma unroll
        for (int c = 0; c < 4; c++) {
            float inv = __frcp_rn(a[c][c]);
            #pragma unroll
            for (int j = 0; j < 8; j++) a[c][j] *= inv;
            #pragma unroll
            for (int r = 0; r < 4; r++) {
                if (r == c) continue;
                float f = a[r][c];
                #pragma unroll
                for (int j = 0; j < 8; j++) a[r][j] = fmaf(-f, a[c][j], a[r][j]);
            }
        }
        float X[4][4], T[4][4], Xr[4][4];
        #pragma unroll
        for (int r = 0; r < 4; r++)
            #pragma unroll
            for (int c = 0; c < 4; c++) X[r][c] = a[r][4 + c];
        #pragma unroll
        for (int r = 0; r < 4; r++)
            #pragma unroll
            for (int c = 0; c < 4; c++) {
                float s = (r == c) ? 2.0f : 0.0f;
                #pragma unroll
                for (int k = 0; k < 4; k++) s = fmaf(-S[r][k], X[k][c], s);
                T[r][c] = s;
            }
        #pragma unroll
        for (int r = 0; r < 4; r++)
            #pragma unroll
            for (int c = 0; c < 4; c++) {
                float s = 0.0f;
                #pragma unroll
                for (int k = 0; k < 4; k++) s = fmaf(X[r][k], T[k][c], s);
                Xr[r][c] = s;
            }
        const float kk = -0.5f * 1.4426950408889634f;   // -0.5*log2(e)
        float C[4][4];
        #pragma unroll
        for (int r = 0; r < 4; r++)
            #pragma unroll
            for (int c = 0; c < 4; c++) C[r][c] = kk * Xr[r][c];
        float mu[4];
        #pragma unroll
        for (int r = 0; r < 4; r++) mu[r] = means[m * 4 + r];

        float w[16];
        w[0] = C[0][0]; w[1] = C[1][1]; w[2] = C[2][2]; w[3] = C[3][3];
        w[4] = 2.0f * C[0][1]; w[5] = 2.0f * C[0][2]; w[6] = 2.0f * C[0][3];
        w[7] = 2.0f * C[1][2]; w[8] = 2.0f * C[1][3]; w[9] = 2.0f * C[2][3];
        #pragma unroll
        for (int r = 0; r < 4; r++) {
            float s = 0.0f;
            #pragma unroll
            for (int c = 0; c < 4; c++) s = fmaf(C[r][c], mu[c], s);
            w[10 + r] = -2.0f * s;
        }
        float q = 0.0f;
        #pragma unroll
        for (int r = 0; r < 4; r++) {
            float s = 0.0f;
            #pragma unroll
            for (int c = 0; c < 4; c++) s = fmaf(C[r][c], mu[c], s);
            q = fmaf(mu[r], s, q);
        }
        w[14] = q;
        w[15] = 0.0f;

        float hi[16], lo[16];
        #pragma unroll
        for (int k = 0; k < 16; k++) {
            __nv_bfloat16 h = __float2bfloat16(w[k]);
            hi[k] = __bfloat162float(h);
            lo[k] = w[k] - hi[k];
        }

        const int t = m >> 3, j = m & 7;
        #pragma unroll
        for (int tg = 0; tg < 4; tg++) {
            u32 h0 = pack_bf16x2(hi[2 * tg],     hi[2 * tg + 1]);
            u32 h1 = pack_bf16x2(hi[2 * tg + 8], hi[2 * tg + 9]);
            u32 l0 = pack_bf16x2(lo[2 * tg],     lo[2 * tg + 1]);
            u32 l1 = pack_bf16x2(lo[2 * tg + 8], lo[2 * tg + 9]);
            const int ln = 4 * j + tg;
            s_tbl[(t * 2 + 0) * 32 + ln] = (ull)h0 | ((ull)h1 << 32);  // hi
            s_tbl[(t * 2 + 1) * 32 + ln] = (ull)l0 | ((ull)l1 << 32);  // lo
        }
        // permuted label: round r = t>>1, odd = t&1, tg = j>>1, p = j&1
        {
            const int r = t >> 1, odd = t & 1, tg = j >> 1, p = j & 1;
            s_lab[r * 16 + tg * 4 + odd * 2 + p] = labels[m];
        }
    }

    // ---- A staging (overlaps with other warps' phase-0 math) ----
    u32* stage = reinterpret_cast<u32*>(smem_raw + SM_STAGE) +
                 wid * RAYS_PER_WARP * STAGE_W;
    const int ray_base = blockIdx.x * RAYS_PER_BLOCK + wid * RAYS_PER_WARP;
    if (lane < 16) {
        const int n = ray_base + lane;
        const float2 o = reinterpret_cast<const float2*>(origins)[n];
        const float2 d = reinterpret_cast<const float2*>(dirs)[n];
        const float p0 = o.x, p1 = o.y, p2 = d.x, p3 = d.y;
        float phi[16];
        phi[0] = p0 * p0; phi[1] = p1 * p1; phi[2] = p2 * p2; phi[3] = p3 * p3;
        phi[4] = p0 * p1; phi[5] = p0 * p2; phi[6] = p0 * p3;
        phi[7] = p1 * p2; phi[8] = p1 * p3; phi[9] = p2 * p3;
        phi[10] = p0; phi[11] = p1; phi[12] = p2; phi[13] = p3;
        phi[14] = 1.0f; phi[15] = 0.0f;
        float hi[16], lo[16];
        #pragma unroll
        for (int k = 0; k < 16; k++) {
            __nv_bfloat16 h = __float2bfloat16(phi[k]);
            hi[k] = __bfloat162float(h);
            lo[k] = phi[k] - hi[k];
        }
        u32* row = stage + lane * STAGE_W;
        #pragma unroll
        for (int wd = 0; wd < 8; wd++) {
            row[wd]      = pack_bf16x2(hi[2 * wd], hi[2 * wd + 1]);  // hi
            row[8 + wd]  = pack_bf16x2(lo[2 * wd], lo[2 * wd + 1]);  // lo
            row[16 + wd] = row[wd];                                   // hi again
        }
    }
    __syncthreads();

    // ================= phase 1: GEMM + exp epilogue =================
    u32 afr[3][4];
    #pragma unroll
    for (int s = 0; s < 3; s++) {
        afr[s][0] = stage[gid * STAGE_W       + 8 * s + tig];
        afr[s][1] = stage[(gid + 8) * STAGE_W + 8 * s + tig];
        afr[s][2] = stage[gid * STAGE_W       + 8 * s + tig + 4];
        afr[s][3] = stage[(gid + 8) * STAGE_W + 8 * s + tig + 4];
    }

    const float4* lab4 = reinterpret_cast<const float4*>(smem_raw + SM_LAB);

    float acc0 = 0.0f, acc1 = 0.0f, acc2 = 0.0f, acc3 = 0.0f;

    #pragma unroll 2
    for (int r = 0; r < NTILES / 2; r++) {
        const ull* bt = s_tbl + r * 128 + lane;
        const ull hhx = bt[0];           // tile 2r   hi
        const ull llx = bt[32];          // tile 2r   lo
        const ull hhy = bt[64];          // tile 2r+1 hi
        const ull lly = bt[96];          // tile 2r+1 lo
        const float4 L = lab4[r * 4 + tig];

        float xA0 = 0.f, xA1 = 0.f, xA2 = 0.f, xA3 = 0.f;
        float xB0 = 0.f, xB1 = 0.f, xB2 = 0.f, xB3 = 0.f;
        mma16816(xA0, xA1, xA2, xA3, afr[0][0], afr[0][1], afr[0][2], afr[0][3],
                 (u32)hhx, (u32)(hhx >> 32));
        mma16816(xB0, xB1, xB2, xB3, afr[1][0], afr[1][1], afr[1][2], afr[1][3],
                 (u32)hhx, (u32)(hhx >> 32));
        mma16816(xB0, xB1, xB2, xB3, afr[2][0], afr[2][1], afr[2][2], afr[2][3],
                 (u32)llx, (u32)(llx >> 32));

        float yA0 = 0.f, yA1 = 0.f, yA2 = 0.f, yA3 = 0.f;
        float yB0 = 0.f, yB1 = 0.f, yB2 = 0.f, yB3 = 0.f;
        mma16816(yA0, yA1, yA2, yA3, afr[0][0], afr[0][1], afr[0][2], afr[0][3],
                 (u32)hhy, (u32)(hhy >> 32));
        mma16816(yB0, yB1, yB2, yB3, afr[1][0], afr[1][1], afr[1][2], afr[1][3],
                 (u32)hhy, (u32)(hhy >> 32));
        mma16816(yB0, yB1, yB2, yB3, afr[2][0], afr[2][1], afr[2][2], afr[2][3],
                 (u32)lly, (u32)(lly >> 32));

        float e;
        asm("ex2.approx.ftz.f32 %0, %1;" : "=f"(e) : "f"(xA0 + xB0));
        acc0 = fmaf(L.x, e, acc0);
        asm("ex2.approx.ftz.f32 %0, %1;" : "=f"(e) : "f"(xA1 + xB1));
        acc1 = fmaf(L.y, e, acc1);
        asm("ex2.approx.ftz.f32 %0, %1;" : "=f"(e) : "f"(xA2 + xB2));
        acc2 = fmaf(L.x, e, acc2);
        asm("ex2.approx.ftz.f32 %0, %1;" : "=f"(e) : "f"(xA3 + xB3));
        acc3 = fmaf(L.y, e, acc3);
        asm("ex2.approx.ftz.f32 %0, %1;" : "=f"(e) : "f"(yA0 + yB0));
        acc0 = fmaf(L.z, e, acc0);
        asm("ex2.approx.ftz.f32 %0, %1;" : "=f"(e) : "f"(yA1 + yB1));
        acc1 = fmaf(L.w, e, acc1);
        asm("ex2.approx.ftz.f32 %0, %1;" : "=f"(e) : "f"(yA2 + yB2));
        acc2 = fmaf(L.z, e, acc2);
        asm("ex2.approx.ftz.f32 %0, %1;" : "=f"(e) : "f"(yA3 + yB3));
        acc3 = fmaf(L.w, e, acc3);
    }

    float accLo = acc0 + acc1;   // ray gid
    float accHi = acc2 + acc3;   // ray gid+8

    #pragma unroll
    for (int d = 1; d < 4; d <<= 1) {
        accLo += __shfl_xor_sync(0xffffffffu, accLo, d);
        accHi += __shfl_xor_sync(0xffffffffu, accHi, d);
    }

    if (tig == 0) {
        const float zL = -accLo * 1.4426950408889634f;
        const float zH = -accHi * 1.4426950408889634f;
        float eL, eH, pL, pH;
        asm("ex2.approx.ftz.f32 %0, %1;" : "=f"(eL) : "f"(zL));
        asm("ex2.approx.ftz.f32 %0, %1;" : "=f"(eH) : "f"(zH));
        asm("rcp.approx.ftz.f32 %0, %1;" : "=f"(pL) : "f"(1.0f + eL));
        asm("rcp.approx.ftz.f32 %0, %1;" : "=f"(pH) : "f"(1.0f + eH));
        out[ray_base + gid]     = pL;
        out[ray_base + gid + 8] = pH;
    }
}

// ---------------------------------------------------------------------------
extern "C" void kernel_launch(void* const* d_in, const int* in_sizes, int n_in,
                              void* d_out, int out_size) {
    const float* origins    = (const float*)d_in[0];
    const float* directions = (const float*)d_in[1];
    const float* means      = (const float*)d_in[2];
    const float* covs       = (const float*)d_in[3];
    const float* labels     = (const float*)d_in[4];
    float* out = (float*)d_out;

    cudaFuncSetAttribute(decoder_kernel,
                         cudaFuncAttributeMaxDynamicSharedMemorySize, SM_TOTAL);
    decoder_kernel<<<N_RAYS / RAYS_PER_BLOCK, 256, SM_TOTAL>>>(
        origins, directions, means, covs, labels, out);
}

// round 13
// speedup vs baseline: 1.4484x; 1.4349x over previous
#include <cuda_runtime.h>
#include <cuda_bf16.h>
#include <cstdint>

#define N_RAYS 32768
#define M_G    1024
#define NTILES (M_G / 8)       // 128 n-tiles of 8 gaussians
#define WARPS  8
#define RAYS_PER_WARP 16
#define RAYS_PER_BLOCK (WARPS * RAYS_PER_WARP)   // 128

typedef unsigned int u32;
typedef unsigned long long ull;

// B fragment table in m16n8k16 lane layout, deduplicated:
//   g_tblB[(t*2 + s)*32 + lane], s=0 -> hi coefficients, s=1 -> lo.
__device__ __align__(16) ull g_tblB[NTILES * 2 * 32];   // 64 KB

// Permuted labels (per 2-tile round r, tig): see prep.
__device__ __align__(16) float g_plab[M_G];

__device__ __forceinline__ u32 pack_bf16x2(float a, float b) {
    __nv_bfloat16 x = __float2bfloat16(a), y = __float2bfloat16(b);
    return (u32)__bfloat16_as_ushort(x) | ((u32)__bfloat16_as_ushort(y) << 16);
}

// ---------------------------------------------------------------------------
// Prep: invert Sigma (fp32 GJ + one Newton step), fold -0.5*log2(e) and mean
// into 16 coefficients, split bf16 hi/lo, emit B fragments + permuted labels.
// ---------------------------------------------------------------------------
__global__ void prep_kernel(const float* __restrict__ means,
                            const float* __restrict__ covs,
                            const float* __restrict__ labels) {
    int m = blockIdx.x * blockDim.x + threadIdx.x;
    if (m >= M_G) return;

    float S[4][4], a[4][8];
    #pragma unroll
    for (int i = 0; i < 4; i++)
        #pragma unroll
        for (int j = 0; j < 4; j++) {
            S[i][j] = covs[m * 16 + i * 4 + j];
            a[i][j] = S[i][j];
        }
    #pragma unroll
    for (int i = 0; i < 4; i++)
        #pragma unroll
        for (int j = 0; j < 4; j++) a[i][4 + j] = (i == j) ? 1.0f : 0.0f;
    #pragma unroll
    for (int c = 0; c < 4; c++) {
        float inv = __frcp_rn(a[c][c]);
        #pragma unroll
        for (int j = 0; j < 8; j++) a[c][j] *= inv;
        #pragma unroll
        for (int r = 0; r < 4; r++) {
            if (r == c) continue;
            float f = a[r][c];
            #pragma unroll
            for (int j = 0; j < 8; j++) a[r][j] = fmaf(-f, a[c][j], a[r][j]);
        }
    }
    float X[4][4], T[4][4], Xr[4][4];
    #pragma unroll
    for (int i = 0; i < 4; i++)
        #pragma unroll
        for (int j = 0; j < 4; j++) X[i][j] = a[i][4 + j];
    #pragma unroll
    for (int i = 0; i < 4; i++)
        #pragma unroll
        for (int j = 0; j < 4; j++) {
            float s = (i == j) ? 2.0f : 0.0f;
            #pragma unroll
            for (int k = 0; k < 4; k++) s = fmaf(-S[i][k], X[k][j], s);
            T[i][j] = s;
        }
    #pragma unroll
    for (int i = 0; i < 4; i++)
        #pragma unroll
        for (int j = 0; j < 4; j++) {
            float s = 0.0f;
            #pragma unroll
            for (int k = 0; k < 4; k++) s = fmaf(X[i][k], T[k][j], s);
            Xr[i][j] = s;
        }
    const float kk = -0.5f * 1.4426950408889634f;   // -0.5*log2(e)
    float C[4][4];
    #pragma unroll
    for (int i = 0; i < 4; i++)
        #pragma unroll
        for (int j = 0; j < 4; j++) C[i][j] = kk * Xr[i][j];
    float mu[4];
    #pragma unroll
    for (int i = 0; i < 4; i++) mu[i] = means[m * 4 + i];

    float w[16];
    w[0] = C[0][0]; w[1] = C[1][1]; w[2] = C[2][2]; w[3] = C[3][3];
    w[4] = 2.0f * C[0][1]; w[5] = 2.0f * C[0][2]; w[6] = 2.0f * C[0][3];
    w[7] = 2.0f * C[1][2]; w[8] = 2.0f * C[1][3]; w[9] = 2.0f * C[2][3];
    #pragma unroll
    for (int i = 0; i < 4; i++) {
        float s = 0.0f;
        #pragma unroll
        for (int j = 0; j < 4; j++) s = fmaf(C[i][j], mu[j], s);
        w[10 + i] = -2.0f * s;
    }
    float q = 0.0f;
    #pragma unroll
    for (int i = 0; i < 4; i++) {
        float s = 0.0f;
        #pragma unroll
        for (int j = 0; j < 4; j++) s = fmaf(C[i][j], mu[j], s);
        q = fmaf(mu[i], s, q);
    }
    w[14] = q;
    w[15] = 0.0f;

    float hi[16], lo[16];
    #pragma unroll
    for (int k = 0; k < 16; k++) {
        __nv_bfloat16 h = __float2bfloat16(w[k]);
        hi[k] = __bfloat162float(h);
        lo[k] = w[k] - hi[k];
    }

    const int t = m >> 3, j = m & 7;
    #pragma unroll
    for (int tig = 0; tig < 4; tig++) {
        u32 h0 = pack_bf16x2(hi[2 * tig],     hi[2 * tig + 1]);
        u32 h1 = pack_bf16x2(hi[2 * tig + 8], hi[2 * tig + 9]);
        u32 l0 = pack_bf16x2(lo[2 * tig],     lo[2 * tig + 1]);
        u32 l1 = pack_bf16x2(lo[2 * tig + 8], lo[2 * tig + 9]);
        const int lane = 4 * j + tig;
        g_tblB[(t * 2 + 0) * 32 + lane] = (ull)h0 | ((ull)h1 << 32);  // hi
        g_tblB[(t * 2 + 1) * 32 + lane] = (ull)l0 | ((ull)l1 << 32);  // lo
    }

    // permuted label: gaussian m = t*8 + 2*tig + p  (p = j&1, tig = (j>>1))
    {
        const int r = t >> 1, odd = t & 1, tg = j >> 1, p = j & 1;
        g_plab[r * 16 + tg * 4 + odd * 2 + p] = labels[m];
    }
}

// ---------------------------------------------------------------------------
// Decoder: 256 threads = 8 warps x 16 rays; 64 rounds of 2 interleaved
// n-tiles (6 MMAs, 8 ex2, 8 FMA per round). Launched with PDL: the ray
// staging prologue overlaps prep's tail; griddepcontrol.wait gates the
// table copy.
// ---------------------------------------------------------------------------
#define SM_TBL   0
#define SM_LAB   (NTILES * 2 * 32 * 8)               // 65536
#define SM_STAGE (SM_LAB + M_G * 4)                  // 69632
#define STAGE_W  25
#define SM_TOTAL (SM_STAGE + RAYS_PER_BLOCK * STAGE_W * 4)  // 82432

extern __shared__ unsigned char smem_raw[];

__device__ __forceinline__ void mma16816(float& c0, float& c1, float& c2, float& c3,
                                         u32 a0, u32 a1, u32 a2, u32 a3,
                                         u32 b0, u32 b1) {
    asm volatile(
        "mma.sync.aligned.m16n8k16.row.col.f32.bf16.bf16.f32 "
        "{%0,%1,%2,%3}, {%4,%5,%6,%7}, {%8,%9}, {%0,%1,%2,%3};"
        : "+f"(c0), "+f"(c1), "+f"(c2), "+f"(c3)
        : "r"(a0), "r"(a1), "r"(a2), "r"(a3), "r"(b0), "r"(b1));
}

__global__ void __launch_bounds__(256, 2)
decoder_kernel(const float* __restrict__ origins,
               const float* __restrict__ dirs,
               float* __restrict__ out) {
    const int tid  = threadIdx.x;
    const int wid  = tid >> 5;
    const int lane = tid & 31;
    const int gid  = lane >> 2;   // row group 0..7
    const int tig  = lane & 3;    // thread-in-group

    // ---- A staging FIRST (independent of prep -> overlaps it under PDL) ----
    u32* stage = reinterpret_cast<u32*>(smem_raw + SM_STAGE) +
                 wid * RAYS_PER_WARP * STAGE_W;
    const int ray_base = blockIdx.x * RAYS_PER_BLOCK + wid * RAYS_PER_WARP;
    if (lane < 16) {
        const int n = ray_base + lane;
        const float2 o = reinterpret_cast<const float2*>(origins)[n];
        const float2 d = reinterpret_cast<const float2*>(dirs)[n];
        const float p0 = o.x, p1 = o.y, p2 = d.x, p3 = d.y;
        float phi[16];
        phi[0] = p0 * p0; phi[1] = p1 * p1; phi[2] = p2 * p2; phi[3] = p3 * p3;
        phi[4] = p0 * p1; phi[5] = p0 * p2; phi[6] = p0 * p3;
        phi[7] = p1 * p2; phi[8] = p1 * p3; phi[9] = p2 * p3;
        phi[10] = p0; phi[11] = p1; phi[12] = p2; phi[13] = p3;
        phi[14] = 1.0f; phi[15] = 0.0f;
        float hi[16], lo[16];
        #pragma unroll
        for (int k = 0; k < 16; k++) {
            __nv_bfloat16 h = __float2bfloat16(phi[k]);
            hi[k] = __bfloat162float(h);
            lo[k] = phi[k] - hi[k];
        }
        u32* row = stage + lane * STAGE_W;
        #pragma unroll
        for (int wd = 0; wd < 8; wd++) {
            row[wd]      = pack_bf16x2(hi[2 * wd], hi[2 * wd + 1]);  // hi
            row[8 + wd]  = pack_bf16x2(lo[2 * wd], lo[2 * wd + 1]);  // lo
            row[16 + wd] = row[wd];                                   // hi again
        }
    }

    // ---- PDL: wait for prep grid before touching its outputs ----
    asm volatile("griddepcontrol.wait;" ::: "memory");

    // ---- cooperative copies: B table (64KB) + permuted labels (4KB) ----
    {
        const uint4* gt = reinterpret_cast<const uint4*>(g_tblB);
        uint4* st = reinterpret_cast<uint4*>(smem_raw + SM_TBL);
        #pragma unroll
        for (int i = 0; i < (NTILES * 2 * 32 * 8 / 16) / 256; i++)
            st[tid + i * 256] = gt[tid + i * 256];
        const uint4* gl = reinterpret_cast<const uint4*>(g_plab);
        uint4* sl = reinterpret_cast<uint4*>(smem_raw + SM_LAB);
        sl[tid] = gl[tid];
    }
    __syncthreads();

    // ---- load A fragments ----
    u32 afr[3][4];
    #pragma unroll
    for (int s = 0; s < 3; s++) {
        afr[s][0] = stage[gid * STAGE_W       + 8 * s + tig];
        afr[s][1] = stage[(gid + 8) * STAGE_W + 8 * s + tig];
        afr[s][2] = stage[gid * STAGE_W       + 8 * s + tig + 4];
        afr[s][3] = stage[(gid + 8) * STAGE_W + 8 * s + tig + 4];
    }

    const ull* tbl = reinterpret_cast<const ull*>(smem_raw + SM_TBL);
    const float4* lab4 = reinterpret_cast<const float4*>(smem_raw + SM_LAB);

    float acc0 = 0.0f, acc1 = 0.0f, acc2 = 0.0f, acc3 = 0.0f;

    #pragma unroll 2
    for (int r = 0; r < NTILES / 2; r++) {
        const ull* bt = tbl + r * 128 + lane;
        const ull hhx = bt[0];           // tile 2r   hi
        const ull llx = bt[32];          // tile 2r   lo
        const ull hhy = bt[64];          // tile 2r+1 hi
        const ull lly = bt[96];          // tile 2r+1 lo
        const float4 L = lab4[r * 4 + tig];

        float xA0 = 0.f, xA1 = 0.f, xA2 = 0.f, xA3 = 0.f;
        float xB0 = 0.f, xB1 = 0.f, xB2 = 0.f, xB3 = 0.f;
        mma16816(xA0, xA1, xA2, xA3, afr[0][0], afr[0][1], afr[0][2], afr[0][3],
                 (u32)hhx, (u32)(hhx >> 32));
        mma16816(xB0, xB1, xB2, xB3, afr[1][0], afr[1][1], afr[1][2], afr[1][3],
                 (u32)hhx, (u32)(hhx >> 32));
        mma16816(xB0, xB1, xB2, xB3, afr[2][0], afr[2][1], afr[2][2], afr[2][3],
                 (u32)llx, (u32)(llx >> 32));

        float yA0 = 0.f, yA1 = 0.f, yA2 = 0.f, yA3 = 0.f;
        float yB0 = 0.f, yB1 = 0.f, yB2 = 0.f, yB3 = 0.f;
        mma16816(yA0, yA1, yA2, yA3, afr[0][0], afr[0][1], afr[0][2], afr[0][3],
                 (u32)hhy, (u32)(hhy >> 32));
        mma16816(yB0, yB1, yB2, yB3, afr[1][0], afr[1][1], afr[1][2], afr[1][3],
                 (u32)hhy, (u32)(hhy >> 32));
        mma16816(yB0, yB1, yB2, yB3, afr[2][0], afr[2][1], afr[2][2], afr[2][3],
                 (u32)lly, (u32)(lly >> 32));

        float e;
        asm("ex2.approx.ftz.f32 %0, %1;" : "=f"(e) : "f"(xA0 + xB0));
        acc0 = fmaf(L.x, e, acc0);
        asm("ex2.approx.ftz.f32 %0, %1;" : "=f"(e) : "f"(xA1 + xB1));
        acc1 = fmaf(L.y, e, acc1);
        asm("ex2.approx.ftz.f32 %0, %1;" : "=f"(e) : "f"(xA2 + xB2));
        acc2 = fmaf(L.x, e, acc2);
        asm("ex2.approx.ftz.f32 %0, %1;" : "=f"(e) : "f"(xA3 + xB3));
        acc3 = fmaf(L.y, e, acc3);
        asm("ex2.approx.ftz.f32 %0, %1;" : "=f"(e) : "f"(yA0 + yB0));
        acc0 = fmaf(L.z, e, acc0);
        asm("ex2.approx.ftz.f32 %0, %1;" : "=f"(e) : "f"(yA1 + yB1));
        acc1 = fmaf(L.w, e, acc1);
        asm("ex2.approx.ftz.f32 %0, %1;" : "=f"(e) : "f"(yA2 + yB2));
        acc2 = fmaf(L.z, e, acc2);
        asm("ex2.approx.ftz.f32 %0, %1;" : "=f"(e) : "f"(yA3 + yB3));
        acc3 = fmaf(L.w, e, acc3);
    }

    float accLo = acc0 + acc1;   // ray gid
    float accHi = acc2 + acc3;   // ray gid+8

    #pragma unroll
    for (int d = 1; d < 4; d <<= 1) {
        accLo += __shfl_xor_sync(0xffffffffu, accLo, d);
        accHi += __shfl_xor_sync(0xffffffffu, accHi, d);
    }

    if (tig == 0) {
        const float zL = -accLo * 1.4426950408889634f;
        const float zH = -accHi * 1.4426950408889634f;
        float eL, eH, pL, pH;
        asm("ex2.approx.ftz.f32 %0, %1;" : "=f"(eL) : "f"(zL));
        asm("ex2.approx.ftz.f32 %0, %1;" : "=f"(eH) : "f"(zH));
        asm("rcp.approx.ftz.f32 %0, %1;" : "=f"(pL) : "f"(1.0f + eL));
        asm("rcp.approx.ftz.f32 %0, %1;" : "=f"(pH) : "f"(1.0f + eH));
        out[ray_base + gid]     = pL;
        out[ray_base + gid + 8] = pH;
    }
}

// ---------------------------------------------------------------------------
extern "C" void kernel_launch(void* const* d_in, const int* in_sizes, int n_in,
                              void* d_out, int out_size) {
    const float* origins    = (const float*)d_in[0];
    const float* directions = (const float*)d_in[1];
    const float* means      = (const float*)d_in[2];
    const float* covs       = (const float*)d_in[3];
    const float* labels     = (const float*)d_in[4];
    float* out = (float*)d_out;

    // prep spread over 32 SMs
    prep_kernel<<<32, 32>>>(means, covs, labels);

    cudaFuncSetAttribute(decoder_kernel,
                         cudaFuncAttributeMaxDynamicSharedMemorySize, SM_TOTAL);

    // PDL launch: decoder prologue overlaps prep tail + launch latency
    cudaLaunchConfig_t cfg = {};
    cfg.gridDim  = dim3(N_RAYS / RAYS_PER_BLOCK, 1, 1);
    cfg.blockDim = dim3(256, 1, 1);
    cfg.dynamicSmemBytes = SM_TOTAL;
    cfg.stream = 0;
    cudaLaunchAttribute attrs[1];
    attrs[0].id = cudaLaunchAttributeProgrammaticStreamSerialization;
    attrs[0].val.programmaticStreamSerializationAllowed = 1;
    cfg.attrs = attrs;
    cfg.numAttrs = 1;
    cudaLaunchKernelEx(&cfg, decoder_kernel, origins, directions, out);
}

// round 14
// speedup vs baseline: 1.6000x; 1.1047x over previous
#include <cuda_runtime.h>
#include <cuda_bf16.h>
#include <cstdint>

#define N_RAYS 32768
#define M_G    1024
#define NTILES (M_G / 8)       // 128 n-tiles of 8 gaussians
#define WARPS  8
#define RAYS_PER_WARP 16
#define RAYS_PER_BLOCK (WARPS * RAYS_PER_WARP)   // 128

typedef unsigned int u32;

// B fragment table, tf32, m16n8k8 lane layout:
//   g_tblB[t*32 + lane] = float4{ w[tig], w[tig+4], w[tig+8], w[tig+12] }
//   for gaussian m = t*8 + (lane>>2), tig = lane&3. Values tf32-rounded.
__device__ __align__(16) float4 g_tblB[NTILES * 32];   // 64 KB

// Permuted labels (per 2-tile round r, tig): see prep.
__device__ __align__(16) float g_plab[M_G];

__device__ __forceinline__ float to_tf32(float x) {
    float r;
    asm("cvt.rna.tf32.f32 %0, %1;" : "=f"(r) : "f"(x));
    return r;
}

// ---------------------------------------------------------------------------
// Prep: invert Sigma (fp32 GJ + one Newton step), fold -0.5*log2(e) and mean
// into 16 coefficients, tf32-round, emit B fragments + permuted labels.
// ---------------------------------------------------------------------------
__global__ void prep_kernel(const float* __restrict__ means,
                            const float* __restrict__ covs,
                            const float* __restrict__ labels) {
    int m = blockIdx.x * blockDim.x + threadIdx.x;
    if (m >= M_G) return;

    float S[4][4], a[4][8];
    #pragma unroll
    for (int i = 0; i < 4; i++)
        #pragma unroll
        for (int j = 0; j < 4; j++) {
            S[i][j] = covs[m * 16 + i * 4 + j];
            a[i][j] = S[i][j];
        }
    #pragma unroll
    for (int i = 0; i < 4; i++)
        #pragma unroll
        for (int j = 0; j < 4; j++) a[i][4 + j] = (i == j) ? 1.0f : 0.0f;
    #pragma unroll
    for (int c = 0; c < 4; c++) {
        float inv = __frcp_rn(a[c][c]);
        #pragma unroll
        for (int j = 0; j < 8; j++) a[c][j] *= inv;
        #pragma unroll
        for (int r = 0; r < 4; r++) {
            if (r == c) continue;
            float f = a[r][c];
            #pragma unroll
            for (int j = 0; j < 8; j++) a[r][j] = fmaf(-f, a[c][j], a[r][j]);
        }
    }
    float X[4][4], T[4][4], Xr[4][4];
    #pragma unroll
    for (int i = 0; i < 4; i++)
        #pragma unroll
        for (int j = 0; j < 4; j++) X[i][j] = a[i][4 + j];
    #pragma unroll
    for (int i = 0; i < 4; i++)
        #pragma unroll
        for (int j = 0; j < 4; j++) {
            float s = (i == j) ? 2.0f : 0.0f;
            #pragma unroll
            for (int k = 0; k < 4; k++) s = fmaf(-S[i][k], X[k][j], s);
            T[i][j] = s;
        }
    #pragma unroll
    for (int i = 0; i < 4; i++)
        #pragma unroll
        for (int j = 0; j < 4; j++) {
            float s = 0.0f;
            #pragma unroll
            for (int k = 0; k < 4; k++) s = fmaf(X[i][k], T[k][j], s);
            Xr[i][j] = s;
        }
    const float kk = -0.5f * 1.4426950408889634f;   // -0.5*log2(e)
    float C[4][4];
    #pragma unroll
    for (int i = 0; i < 4; i++)
        #pragma unroll
        for (int j = 0; j < 4; j++) C[i][j] = kk * Xr[i][j];
    float mu[4];
    #pragma unroll
    for (int i = 0; i < 4; i++) mu[i] = means[m * 4 + i];

    float w[16];
    w[0] = C[0][0]; w[1] = C[1][1]; w[2] = C[2][2]; w[3] = C[3][3];
    w[4] = 2.0f * C[0][1]; w[5] = 2.0f * C[0][2]; w[6] = 2.0f * C[0][3];
    w[7] = 2.0f * C[1][2]; w[8] = 2.0f * C[1][3]; w[9] = 2.0f * C[2][3];
    #pragma unroll
    for (int i = 0; i < 4; i++) {
        float s = 0.0f;
        #pragma unroll
        for (int j = 0; j < 4; j++) s = fmaf(C[i][j], mu[j], s);
        w[10 + i] = -2.0f * s;
    }
    float q = 0.0f;
    #pragma unroll
    for (int i = 0; i < 4; i++) {
        float s = 0.0f;
        #pragma unroll
        for (int j = 0; j < 4; j++) s = fmaf(C[i][j], mu[j], s);
        q = fmaf(mu[i], s, q);
    }
    w[14] = q;
    w[15] = 0.0f;

    #pragma unroll
    for (int k = 0; k < 16; k++) w[k] = to_tf32(w[k]);

    const int t = m >> 3, j = m & 7;
    #pragma unroll
    for (int tg = 0; tg < 4; tg++) {
        g_tblB[t * 32 + 4 * j + tg] =
            make_float4(w[tg], w[tg + 4], w[tg + 8], w[tg + 12]);
    }

    // permuted label: round r = t>>1, odd = t&1, tg = j>>1, p = j&1
    {
        const int r = t >> 1, odd = t & 1, tg = j >> 1, p = j & 1;
        g_plab[r * 16 + tg * 4 + odd * 2 + p] = labels[m];
    }
}

// ---------------------------------------------------------------------------
// Decoder: 256 threads = 8 warps x 16 rays; 64 rounds of 2 interleaved
// n-tiles, each tile = 2x m16n8k8 tf32 MMA (K=16) + ex2/label epilogue.
// PDL launch: ray staging overlaps prep tail; griddepcontrol.wait gates the
// table copy.
// ---------------------------------------------------------------------------
#define SM_TBL   0
#define SM_LAB   (NTILES * 32 * 16)                 // 65536
#define SM_STAGE (SM_LAB + M_G * 4)                 // 69632
#define STAGE_W  17                                 // padded words per ray
#define SM_TOTAL (SM_STAGE + RAYS_PER_BLOCK * STAGE_W * 4)  // 78336

extern __shared__ unsigned char smem_raw[];

__device__ __forceinline__ void mma_tf32(float& c0, float& c1, float& c2, float& c3,
                                         u32 a0, u32 a1, u32 a2, u32 a3,
                                         u32 b0, u32 b1) {
    asm volatile(
        "mma.sync.aligned.m16n8k8.row.col.f32.tf32.tf32.f32 "
        "{%0,%1,%2,%3}, {%4,%5,%6,%7}, {%8,%9}, {%0,%1,%2,%3};"
        : "+f"(c0), "+f"(c1), "+f"(c2), "+f"(c3)
        : "r"(a0), "r"(a1), "r"(a2), "r"(a3), "r"(b0), "r"(b1));
}

__global__ void __launch_bounds__(256, 2)
decoder_kernel(const float* __restrict__ origins,
               const float* __restrict__ dirs,
               float* __restrict__ out) {
    const int tid  = threadIdx.x;
    const int wid  = tid >> 5;
    const int lane = tid & 31;
    const int gid  = lane >> 2;   // row group 0..7
    const int tig  = lane & 3;    // thread-in-group

    // ---- A staging FIRST (independent of prep -> overlaps it under PDL) ----
    u32* stage = reinterpret_cast<u32*>(smem_raw + SM_STAGE) +
                 wid * RAYS_PER_WARP * STAGE_W;
    const int ray_base = blockIdx.x * RAYS_PER_BLOCK + wid * RAYS_PER_WARP;
    if (lane < 16) {
        const int n = ray_base + lane;
        const float2 o = reinterpret_cast<const float2*>(origins)[n];
        const float2 d = reinterpret_cast<const float2*>(dirs)[n];
        const float p0 = o.x, p1 = o.y, p2 = d.x, p3 = d.y;
        float phi[16];
        phi[0] = p0 * p0; phi[1] = p1 * p1; phi[2] = p2 * p2; phi[3] = p3 * p3;
        phi[4] = p0 * p1; phi[5] = p0 * p2; phi[6] = p0 * p3;
        phi[7] = p1 * p2; phi[8] = p1 * p3; phi[9] = p2 * p3;
        phi[10] = p0; phi[11] = p1; phi[12] = p2; phi[13] = p3;
        phi[14] = 1.0f; phi[15] = 0.0f;
        u32* row = stage + lane * STAGE_W;
        #pragma unroll
        for (int k = 0; k < 16; k++)
            row[k] = __float_as_uint(to_tf32(phi[k]));
    }

    // ---- PDL: wait for prep grid before touching its outputs ----
    asm volatile("griddepcontrol.wait;" ::: "memory");

    // ---- cooperative copies: B table (64KB) + permuted labels (4KB) ----
    {
        const uint4* gt = reinterpret_cast<const uint4*>(g_tblB);
        uint4* st = reinterpret_cast<uint4*>(smem_raw + SM_TBL);
        #pragma unroll
        for (int i = 0; i < (NTILES * 32 * 16 / 16) / 256; i++)
            st[tid + i * 256] = gt[tid + i * 256];
        const uint4* gl = reinterpret_cast<const uint4*>(g_plab);
        uint4* sl = reinterpret_cast<uint4*>(smem_raw + SM_LAB);
        sl[tid] = gl[tid];
    }
    __syncthreads();

    // ---- load A fragments (8 words, once) ----
    u32 afr[2][4];
    #pragma unroll
    for (int s = 0; s < 2; s++) {
        afr[s][0] = stage[gid * STAGE_W       + 8 * s + tig];
        afr[s][1] = stage[(gid + 8) * STAGE_W + 8 * s + tig];
        afr[s][2] = stage[gid * STAGE_W       + 8 * s + tig + 4];
        afr[s][3] = stage[(gid + 8) * STAGE_W + 8 * s + tig + 4];
    }

    const float4* tbl = reinterpret_cast<const float4*>(smem_raw + SM_TBL);
    const float4* lab4 = reinterpret_cast<const float4*>(smem_raw + SM_LAB);

    float acc0 = 0.0f, acc1 = 0.0f, acc2 = 0.0f, acc3 = 0.0f;

    #pragma unroll 4
    for (int r = 0; r < NTILES / 2; r++) {
        const float4 bX = tbl[(2 * r)     * 32 + lane];   // tile 2r
        const float4 bY = tbl[(2 * r + 1) * 32 + lane];   // tile 2r+1
        const float4 L = lab4[r * 4 + tig];

        // tile X: 2 k8 MMAs, accumulate in-register
        float cX0 = 0.f, cX1 = 0.f, cX2 = 0.f, cX3 = 0.f;
        mma_tf32(cX0, cX1, cX2, cX3, afr[0][0], afr[0][1], afr[0][2], afr[0][3],
                 __float_as_uint(bX.x), __float_as_uint(bX.y));
        mma_tf32(cX0, cX1, cX2, cX3, afr[1][0], afr[1][1], afr[1][2], afr[1][3],
                 __float_as_uint(bX.z), __float_as_uint(bX.w));

        // tile Y
        float cY0 = 0.f, cY1 = 0.f, cY2 = 0.f, cY3 = 0.f;
        mma_tf32(cY0, cY1, cY2, cY3, afr[0][0], afr[0][1], afr[0][2], afr[0][3],
                 __float_as_uint(bY.x), __float_as_uint(bY.y));
        mma_tf32(cY0, cY1, cY2, cY3, afr[1][0], afr[1][1], afr[1][2], afr[1][3],
                 __float_as_uint(bY.z), __float_as_uint(bY.w));

        float e;
        asm("ex2.approx.ftz.f32 %0, %1;" : "=f"(e) : "f"(cX0));
        acc0 = fmaf(L.x, e, acc0);
        asm("ex2.approx.ftz.f32 %0, %1;" : "=f"(e) : "f"(cX1));
        acc1 = fmaf(L.y, e, acc1);
        asm("ex2.approx.ftz.f32 %0, %1;" : "=f"(e) : "f"(cX2));
        acc2 = fmaf(L.x, e, acc2);
        asm("ex2.approx.ftz.f32 %0, %1;" : "=f"(e) : "f"(cX3));
        acc3 = fmaf(L.y, e, acc3);
        asm("ex2.approx.ftz.f32 %0, %1;" : "=f"(e) : "f"(cY0));
        acc0 = fmaf(L.z, e, acc0);
        asm("ex2.approx.ftz.f32 %0, %1;" : "=f"(e) : "f"(cY1));
        acc1 = fmaf(L.w, e, acc1);
        asm("ex2.approx.ftz.f32 %0, %1;" : "=f"(e) : "f"(cY2));
        acc2 = fmaf(L.z, e, acc2);
        asm("ex2.approx.ftz.f32 %0, %1;" : "=f"(e) : "f"(cY3));
        acc3 = fmaf(L.w, e, acc3);
    }

    float accLo = acc0 + acc1;   // ray gid
    float accHi = acc2 + acc3;   // ray gid+8

    #pragma unroll
    for (int d = 1; d < 4; d <<= 1) {
        accLo += __shfl_xor_sync(0xffffffffu, accLo, d);
        accHi += __shfl_xor_sync(0xffffffffu, accHi, d);
    }

    if (tig == 0) {
        const float zL = -accLo * 1.4426950408889634f;
        const float zH = -accHi * 1.4426950408889634f;
        float eL, eH, pL, pH;
        asm("ex2.approx.ftz.f32 %0, %1;" : "=f"(eL) : "f"(zL));
        asm("ex2.approx.ftz.f32 %0, %1;" : "=f"(eH) : "f"(zH));
        asm("rcp.approx.ftz.f32 %0, %1;" : "=f"(pL) : "f"(1.0f + eL));
        asm("rcp.approx.ftz.f32 %0, %1;" : "=f"(pH) : "f"(1.0f + eH));
        out[ray_base + gid]     = pL;
        out[ray_base + gid + 8] = pH;
    }
}

// ---------------------------------------------------------------------------
extern "C" void kernel_launch(void* const* d_in, const int* in_sizes, int n_in,
                              void* d_out, int out_size) {
    const float* origins    = (const float*)d_in[0];
    const float* directions = (const float*)d_in[1];
    const float* means      = (const float*)d_in[2];
    const float* covs       = (const float*)d_in[3];
    const float* labels     = (const float*)d_in[4];
    float* out = (float*)d_out;

    prep_kernel<<<32, 32>>>(means, covs, labels);

    cudaFuncSetAttribute(decoder_kernel,
                         cudaFuncAttributeMaxDynamicSharedMemorySize, SM_TOTAL);

    cudaLaunchConfig_t cfg = {};
    cfg.gridDim  = dim3(N_RAYS / RAYS_PER_BLOCK, 1, 1);
    cfg.blockDim = dim3(256, 1, 1);
    cfg.dynamicSmemBytes = SM_TOTAL;
    cfg.stream = 0;
    cudaLaunchAttribute attrs[1];
    attrs[0].id = cudaLaunchAttributeProgrammaticStreamSerialization;
    attrs[0].val.programmaticStreamSerializationAllowed = 1;
    cfg.attrs = attrs;
    cfg.numAttrs = 1;
    cudaLaunchKernelEx(&cfg, decoder_kernel, origins, directions, out);
}

// round 15
// speedup vs baseline: 1.6212x; 1.0133x over previous
#include <cuda_runtime.h>
#include <cuda_bf16.h>
#include <cstdint>

#define N_RAYS 32768
#define M_G    1024
#define NTILES (M_G / 8)       // 128 n-tiles of 8 gaussians
#define WARPS  8
#define RAYS_PER_WARP 16
#define RAYS_PER_BLOCK (WARPS * RAYS_PER_WARP)   // 128

typedef unsigned int u32;

// B fragment table, tf32, m16n8k8 lane layout:
//   g_tblB[t*32 + lane] = float4{ w[tig], w[tig+4], w[tig+8], w[tig+12] }
//   for gaussian m = t*8 + (lane>>2), tig = lane&3. Values tf32-rounded.
__device__ __align__(16) float4 g_tblB[NTILES * 32];   // 64 KB

// Permuted labels (per 2-tile round r, tig): see prep.
__device__ __align__(16) float g_plab[M_G];

__device__ __forceinline__ float to_tf32(float x) {
    float r;
    asm("cvt.rna.tf32.f32 %0, %1;" : "=f"(r) : "f"(x));
    return r;
}

// ---------------------------------------------------------------------------
// Prep: invert Sigma (fp32 GJ + one Newton step), fold -0.5*log2(e) and mean
// into 16 coefficients, tf32-round, emit B fragments + permuted labels.
// ---------------------------------------------------------------------------
__global__ void prep_kernel(const float* __restrict__ means,
                            const float* __restrict__ covs,
                            const float* __restrict__ labels) {
    int m = blockIdx.x * blockDim.x + threadIdx.x;
    if (m >= M_G) return;

    float S[4][4], a[4][8];
    #pragma unroll
    for (int i = 0; i < 4; i++)
        #pragma unroll
        for (int j = 0; j < 4; j++) {
            S[i][j] = covs[m * 16 + i * 4 + j];
            a[i][j] = S[i][j];
        }
    #pragma unroll
    for (int i = 0; i < 4; i++)
        #pragma unroll
        for (int j = 0; j < 4; j++) a[i][4 + j] = (i == j) ? 1.0f : 0.0f;
    #pragma unroll
    for (int c = 0; c < 4; c++) {
        float inv = __frcp_rn(a[c][c]);
        #pragma unroll
        for (int j = 0; j < 8; j++) a[c][j] *= inv;
        #pragma unroll
        for (int r = 0; r < 4; r++) {
            if (r == c) continue;
            float f = a[r][c];
            #pragma unroll
            for (int j = 0; j < 8; j++) a[r][j] = fmaf(-f, a[c][j], a[r][j]);
        }
    }
    float X[4][4], T[4][4], Xr[4][4];
    #pragma unroll
    for (int i = 0; i < 4; i++)
        #pragma unroll
        for (int j = 0; j < 4; j++) X[i][j] = a[i][4 + j];
    #pragma unroll
    for (int i = 0; i < 4; i++)
        #pragma unroll
        for (int j = 0; j < 4; j++) {
            float s = (i == j) ? 2.0f : 0.0f;
            #pragma unroll
            for (int k = 0; k < 4; k++) s = fmaf(-S[i][k], X[k][j], s);
            T[i][j] = s;
        }
    #pragma unroll
    for (int i = 0; i < 4; i++)
        #pragma unroll
        for (int j = 0; j < 4; j++) {
            float s = 0.0f;
            #pragma unroll
            for (int k = 0; k < 4; k++) s = fmaf(X[i][k], T[k][j], s);
            Xr[i][j] = s;
        }
    const float kk = -0.5f * 1.4426950408889634f;   // -0.5*log2(e)
    float C[4][4];
    #pragma unroll
    for (int i = 0; i < 4; i++)
        #pragma unroll
        for (int j = 0; j < 4; j++) C[i][j] = kk * Xr[i][j];
    float mu[4];
    #pragma unroll
    for (int i = 0; i < 4; i++) mu[i] = means[m * 4 + i];

    float w[16];
    w[0] = C[0][0]; w[1] = C[1][1]; w[2] = C[2][2]; w[3] = C[3][3];
    w[4] = 2.0f * C[0][1]; w[5] = 2.0f * C[0][2]; w[6] = 2.0f * C[0][3];
    w[7] = 2.0f * C[1][2]; w[8] = 2.0f * C[1][3]; w[9] = 2.0f * C[2][3];
    #pragma unroll
    for (int i = 0; i < 4; i++) {
        float s = 0.0f;
        #pragma unroll
        for (int j = 0; j < 4; j++) s = fmaf(C[i][j], mu[j], s);
        w[10 + i] = -2.0f * s;
    }
    float q = 0.0f;
    #pragma unroll
    for (int i = 0; i < 4; i++) {
        float s = 0.0f;
        #pragma unroll
        for (int j = 0; j < 4; j++) s = fmaf(C[i][j], mu[j], s);
        q = fmaf(mu[i], s, q);
    }
    w[14] = q;
    w[15] = 0.0f;

    #pragma unroll
    for (int k = 0; k < 16; k++) w[k] = to_tf32(w[k]);

    const int t = m >> 3, j = m & 7;
    #pragma unroll
    for (int tg = 0; tg < 4; tg++) {
        g_tblB[t * 32 + 4 * j + tg] =
            make_float4(w[tg], w[tg + 4], w[tg + 8], w[tg + 12]);
    }

    // permuted label: round r = t>>1, odd = t&1, tg = j>>1, p = j&1
    {
        const int r = t >> 1, odd = t & 1, tg = j >> 1, p = j & 1;
        g_plab[r * 16 + tg * 4 + odd * 2 + p] = labels[m];
    }
}

// ---------------------------------------------------------------------------
// Decoder: 256 threads = 8 warps x 16 rays; 64 rounds of 2 n-tiles (tf32
// m16n8k8 x2 per tile), SOFTWARE PIPELINED: round r's MMAs issue before
// round r-1's ex2/label epilogue consumes the previous results.
// PDL launch: ray staging overlaps prep tail.
// ---------------------------------------------------------------------------
#define SM_TBL   0
#define SM_LAB   (NTILES * 32 * 16)                 // 65536
#define SM_STAGE (SM_LAB + M_G * 4)                 // 69632
#define STAGE_W  17                                 // padded words per ray
#define SM_TOTAL (SM_STAGE + RAYS_PER_BLOCK * STAGE_W * 4)  // 78336

extern __shared__ unsigned char smem_raw[];

__device__ __forceinline__ void mma_tf32(float& c0, float& c1, float& c2, float& c3,
                                         u32 a0, u32 a1, u32 a2, u32 a3,
                                         u32 b0, u32 b1) {
    asm volatile(
        "mma.sync.aligned.m16n8k8.row.col.f32.tf32.tf32.f32 "
        "{%0,%1,%2,%3}, {%4,%5,%6,%7}, {%8,%9}, {%0,%1,%2,%3};"
        : "+f"(c0), "+f"(c1), "+f"(c2), "+f"(c3)
        : "r"(a0), "r"(a1), "r"(a2), "r"(a3), "r"(b0), "r"(b1));
}

__global__ void __launch_bounds__(256, 2)
decoder_kernel(const float* __restrict__ origins,
               const float* __restrict__ dirs,
               float* __restrict__ out) {
    const int tid  = threadIdx.x;
    const int wid  = tid >> 5;
    const int lane = tid & 31;
    const int gid  = lane >> 2;   // row group 0..7
    const int tig  = lane & 3;    // thread-in-group

    // ---- A staging FIRST (independent of prep -> overlaps it under PDL) ----
    u32* stage = reinterpret_cast<u32*>(smem_raw + SM_STAGE) +
                 wid * RAYS_PER_WARP * STAGE_W;
    const int ray_base = blockIdx.x * RAYS_PER_BLOCK + wid * RAYS_PER_WARP;
    if (lane < 16) {
        const int n = ray_base + lane;
        const float2 o = reinterpret_cast<const float2*>(origins)[n];
        const float2 d = reinterpret_cast<const float2*>(dirs)[n];
        const float p0 = o.x, p1 = o.y, p2 = d.x, p3 = d.y;
        float phi[16];
        phi[0] = p0 * p0; phi[1] = p1 * p1; phi[2] = p2 * p2; phi[3] = p3 * p3;
        phi[4] = p0 * p1; phi[5] = p0 * p2; phi[6] = p0 * p3;
        phi[7] = p1 * p2; phi[8] = p1 * p3; phi[9] = p2 * p3;
        phi[10] = p0; phi[11] = p1; phi[12] = p2; phi[13] = p3;
        phi[14] = 1.0f; phi[15] = 0.0f;
        u32* row = stage + lane * STAGE_W;
        #pragma unroll
        for (int k = 0; k < 16; k++)
            row[k] = __float_as_uint(to_tf32(phi[k]));
    }

    // ---- PDL: wait for prep grid before touching its outputs ----
    asm volatile("griddepcontrol.wait;" ::: "memory");

    // ---- cooperative copies: B table (64KB) + permuted labels (4KB) ----
    {
        const uint4* gt = reinterpret_cast<const uint4*>(g_tblB);
        uint4* st = reinterpret_cast<uint4*>(smem_raw + SM_TBL);
        #pragma unroll
        for (int i = 0; i < (NTILES * 32 * 16 / 16) / 256; i++)
            st[tid + i * 256] = gt[tid + i * 256];
        const uint4* gl = reinterpret_cast<const uint4*>(g_plab);
        uint4* sl = reinterpret_cast<uint4*>(smem_raw + SM_LAB);
        sl[tid] = gl[tid];
    }
    __syncthreads();

    // ---- load A fragments (8 words, once) ----
    u32 afr[2][4];
    #pragma unroll
    for (int s = 0; s < 2; s++) {
        afr[s][0] = stage[gid * STAGE_W       + 8 * s + tig];
        afr[s][1] = stage[(gid + 8) * STAGE_W + 8 * s + tig];
        afr[s][2] = stage[gid * STAGE_W       + 8 * s + tig + 4];
        afr[s][3] = stage[(gid + 8) * STAGE_W + 8 * s + tig + 4];
    }

    const float4* tbl = reinterpret_cast<const float4*>(smem_raw + SM_TBL);
    const float4* lab4 = reinterpret_cast<const float4*>(smem_raw + SM_LAB);

    float acc0 = 0.0f, acc1 = 0.0f, acc2 = 0.0f, acc3 = 0.0f;

    // pipeline registers: previous round's MMA results + labels
    float pX0, pX1, pX2, pX3, pY0, pY1, pY2, pY3;
    float4 pL;

    // ---- prologue: round 0 MMAs ----
    {
        const float4 bX = tbl[lane];
        const float4 bY = tbl[32 + lane];
        pL = lab4[tig];
        float c0 = 0.f, c1 = 0.f, c2 = 0.f, c3 = 0.f;
        mma_tf32(c0, c1, c2, c3, afr[0][0], afr[0][1], afr[0][2], afr[0][3],
                 __float_as_uint(bX.x), __float_as_uint(bX.y));
        mma_tf32(c0, c1, c2, c3, afr[1][0], afr[1][1], afr[1][2], afr[1][3],
                 __float_as_uint(bX.z), __float_as_uint(bX.w));
        pX0 = c0; pX1 = c1; pX2 = c2; pX3 = c3;
        float d0 = 0.f, d1 = 0.f, d2 = 0.f, d3 = 0.f;
        mma_tf32(d0, d1, d2, d3, afr[0][0], afr[0][1], afr[0][2], afr[0][3],
                 __float_as_uint(bY.x), __float_as_uint(bY.y));
        mma_tf32(d0, d1, d2, d3, afr[1][0], afr[1][1], afr[1][2], afr[1][3],
                 __float_as_uint(bY.z), __float_as_uint(bY.w));
        pY0 = d0; pY1 = d1; pY2 = d2; pY3 = d3;
    }

    // ---- pipelined main loop: MMAs(r) then epilogue(r-1) ----
    #pragma unroll 4
    for (int r = 1; r < NTILES / 2; r++) {
        const float4 bX = tbl[(2 * r)     * 32 + lane];
        const float4 bY = tbl[(2 * r + 1) * 32 + lane];
        const float4 L = lab4[r * 4 + tig];

        float cX0 = 0.f, cX1 = 0.f, cX2 = 0.f, cX3 = 0.f;
        mma_tf32(cX0, cX1, cX2, cX3, afr[0][0], afr[0][1], afr[0][2], afr[0][3],
                 __float_as_uint(bX.x), __float_as_uint(bX.y));
        mma_tf32(cX0, cX1, cX2, cX3, afr[1][0], afr[1][1], afr[1][2], afr[1][3],
                 __float_as_uint(bX.z), __float_as_uint(bX.w));
        float cY0 = 0.f, cY1 = 0.f, cY2 = 0.f, cY3 = 0.f;
        mma_tf32(cY0, cY1, cY2, cY3, afr[0][0], afr[0][1], afr[0][2], afr[0][3],
                 __float_as_uint(bY.x), __float_as_uint(bY.y));
        mma_tf32(cY0, cY1, cY2, cY3, afr[1][0], afr[1][1], afr[1][2], afr[1][3],
                 __float_as_uint(bY.z), __float_as_uint(bY.w));

        // epilogue for round r-1 (overlaps the in-flight MMAs above)
        float e;
        asm("ex2.approx.ftz.f32 %0, %1;" : "=f"(e) : "f"(pX0));
        acc0 = fmaf(pL.x, e, acc0);
        asm("ex2.approx.ftz.f32 %0, %1;" : "=f"(e) : "f"(pX1));
        acc1 = fmaf(pL.y, e, acc1);
        asm("ex2.approx.ftz.f32 %0, %1;" : "=f"(e) : "f"(pX2));
        acc2 = fmaf(pL.x, e, acc2);
        asm("ex2.approx.ftz.f32 %0, %1;" : "=f"(e) : "f"(pX3));
        acc3 = fmaf(pL.y, e, acc3);
        asm("ex2.approx.ftz.f32 %0, %1;" : "=f"(e) : "f"(pY0));
        acc0 = fmaf(pL.z, e, acc0);
        asm("ex2.approx.ftz.f32 %0, %1;" : "=f"(e) : "f"(pY1));
        acc1 = fmaf(pL.w, e, acc1);
        asm("ex2.approx.ftz.f32 %0, %1;" : "=f"(e) : "f"(pY2));
        acc2 = fmaf(pL.z, e, acc2);
        asm("ex2.approx.ftz.f32 %0, %1;" : "=f"(e) : "f"(pY3));
        acc3 = fmaf(pL.w, e, acc3);

        // rotate pipeline registers
        pX0 = cX0; pX1 = cX1; pX2 = cX2; pX3 = cX3;
        pY0 = cY0; pY1 = cY1; pY2 = cY2; pY3 = cY3;
        pL = L;
    }

    // ---- drain: epilogue for the last round ----
    {
        float e;
        asm("ex2.approx.ftz.f32 %0, %1;" : "=f"(e) : "f"(pX0));
        acc0 = fmaf(pL.x, e, acc0);
        asm("ex2.approx.ftz.f32 %0, %1;" : "=f"(e) : "f"(pX1));
        acc1 = fmaf(pL.y, e, acc1);
        asm("ex2.approx.ftz.f32 %0, %1;" : "=f"(e) : "f"(pX2));
        acc2 = fmaf(pL.x, e, acc2);
        asm("ex2.approx.ftz.f32 %0, %1;" : "=f"(e) : "f"(pX3));
        acc3 = fmaf(pL.y, e, acc3);
        asm("ex2.approx.ftz.f32 %0, %1;" : "=f"(e) : "f"(pY0));
        acc0 = fmaf(pL.z, e, acc0);
        asm("ex2.approx.ftz.f32 %0, %1;" : "=f"(e) : "f"(pY1));
        acc1 = fmaf(pL.w, e, acc1);
        asm("ex2.approx.ftz.f32 %0, %1;" : "=f"(e) : "f"(pY2));
        acc2 = fmaf(pL.z, e, acc2);
        asm("ex2.approx.ftz.f32 %0, %1;" : "=f"(e) : "f"(pY3));
        acc3 = fmaf(pL.w, e, acc3);
    }

    float accLo = acc0 + acc1;   // ray gid
    float accHi = acc2 + acc3;   // ray gid+8

    #pragma unroll
    for (int d = 1; d < 4; d <<= 1) {
        accLo += __shfl_xor_sync(0xffffffffu, accLo, d);
        accHi += __shfl_xor_sync(0xffffffffu, accHi, d);
    }

    if (tig == 0) {
        const float zL = -accLo * 1.4426950408889634f;
        const float zH = -accHi * 1.4426950408889634f;
        float eL, eH, pL2, pH2;
        asm("ex2.approx.ftz.f32 %0, %1;" : "=f"(eL) : "f"(zL));
        asm("ex2.approx.ftz.f32 %0, %1;" : "=f"(eH) : "f"(zH));
        asm("rcp.approx.ftz.f32 %0, %1;" : "=f"(pL2) : "f"(1.0f + eL));
        asm("rcp.approx.ftz.f32 %0, %1;" : "=f"(pH2) : "f"(1.0f + eH));
        out[ray_base + gid]     = pL2;
        out[ray_base + gid + 8] = pH2;
    }
}

// ---------------------------------------------------------------------------
extern "C" void kernel_launch(void* const* d_in, const int* in_sizes, int n_in,
                              void* d_out, int out_size) {
    const float* origins    = (const float*)d_in[0];
    const float* directions = (const float*)d_in[1];
    const float* means      = (const float*)d_in[2];
    const float* covs       = (const float*)d_in[3];
    const float* labels     = (const float*)d_in[4];
    float* out = (float*)d_out;

    prep_kernel<<<32, 32>>>(means, covs, labels);

    cudaFuncSetAttribute(decoder_kernel,
                         cudaFuncAttributeMaxDynamicSharedMemorySize, SM_TOTAL);

    cudaLaunchConfig_t cfg = {};
    cfg.gridDim  = dim3(N_RAYS / RAYS_PER_BLOCK, 1, 1);
    cfg.blockDim = dim3(256, 1, 1);
    cfg.dynamicSmemBytes = SM_TOTAL;
    cfg.stream = 0;
    cudaLaunchAttribute attrs[1];
    attrs[0].id = cudaLaunchAttributeProgrammaticStreamSerialization;
    attrs[0].val.programmaticStreamSerializationAllowed = 1;
    cfg.attrs = attrs;
    cfg.numAttrs = 1;
    cudaLaunchKernelEx(&cfg, decoder_kernel, origins, directions, out);
}

// round 16
// speedup vs baseline: 1.8174x; 1.1210x over previous
#include <cuda_runtime.h>
#include <cuda_bf16.h>
#include <cstdint>

#define N_RAYS 32768
#define M_G    1024
#define NTILES (M_G / 8)       // 128 n-tiles of 8 gaussians
#define WARPS  4
#define RAYS_PER_WARP 32       // two m16 row-groups per warp
#define RAYS_PER_BLOCK (WARPS * RAYS_PER_WARP)   // 128

typedef unsigned int u32;

// B fragment table, tf32, m16n8k8 lane layout:
//   g_tblB[t*32 + lane] = float4{ w[tig], w[tig+4], w[tig+8], w[tig+12] }
//   for gaussian m = t*8 + (lane>>2), tig = lane&3. Values tf32-rounded.
__device__ __align__(16) float4 g_tblB[NTILES * 32];   // 64 KB

// Permuted labels (per 2-tile round r, tig): see prep.
__device__ __align__(16) float g_plab[M_G];

__device__ __forceinline__ float to_tf32(float x) {
    float r;
    asm("cvt.rna.tf32.f32 %0, %1;" : "=f"(r) : "f"(x));
    return r;
}

// ---------------------------------------------------------------------------
// Prep: invert Sigma (fp32 GJ + one Newton step), fold -0.5*log2(e) and mean
// into 16 coefficients, tf32-round, emit B fragments + permuted labels.
// ---------------------------------------------------------------------------
__global__ void prep_kernel(const float* __restrict__ means,
                            const float* __restrict__ covs,
                            const float* __restrict__ labels) {
    int m = blockIdx.x * blockDim.x + threadIdx.x;
    if (m >= M_G) return;

    float S[4][4], a[4][8];
    #pragma unroll
    for (int i = 0; i < 4; i++)
        #pragma unroll
        for (int j = 0; j < 4; j++) {
            S[i][j] = covs[m * 16 + i * 4 + j];
            a[i][j] = S[i][j];
        }
    #pragma unroll
    for (int i = 0; i < 4; i++)
        #pragma unroll
        for (int j = 0; j < 4; j++) a[i][4 + j] = (i == j) ? 1.0f : 0.0f;
    #pragma unroll
    for (int c = 0; c < 4; c++) {
        float inv = __frcp_rn(a[c][c]);
        #pragma unroll
        for (int j = 0; j < 8; j++) a[c][j] *= inv;
        #pragma unroll
        for (int r = 0; r < 4; r++) {
            if (r == c) continue;
            float f = a[r][c];
            #pragma unroll
            for (int j = 0; j < 8; j++) a[r][j] = fmaf(-f, a[c][j], a[r][j]);
        }
    }
    float X[4][4], T[4][4], Xr[4][4];
    #pragma unroll
    for (int i = 0; i < 4; i++)
        #pragma unroll
        for (int j = 0; j < 4; j++) X[i][j] = a[i][4 + j];
    #pragma unroll
    for (int i = 0; i < 4; i++)
        #pragma unroll
        for (int j = 0; j < 4; j++) {
            float s = (i == j) ? 2.0f : 0.0f;
            #pragma unroll
            for (int k = 0; k < 4; k++) s = fmaf(-S[i][k], X[k][j], s);
            T[i][j] = s;
        }
    #pragma unroll
    for (int i = 0; i < 4; i++)
        #pragma unroll
        for (int j = 0; j < 4; j++) {
            float s = 0.0f;
            #pragma unroll
            for (int k = 0; k < 4; k++) s = fmaf(X[i][k], T[k][j], s);
            Xr[i][j] = s;
        }
    const float kk = -0.5f * 1.4426950408889634f;   // -0.5*log2(e)
    float C[4][4];
    #pragma unroll
    for (int i = 0; i < 4; i++)
        #pragma unroll
        for (int j = 0; j < 4; j++) C[i][j] = kk * Xr[i][j];
    float mu[4];
    #pragma unroll
    for (int i = 0; i < 4; i++) mu[i] = means[m * 4 + i];

    float w[16];
    w[0] = C[0][0]; w[1] = C[1][1]; w[2] = C[2][2]; w[3] = C[3][3];
    w[4] = 2.0f * C[0][1]; w[5] = 2.0f * C[0][2]; w[6] = 2.0f * C[0][3];
    w[7] = 2.0f * C[1][2]; w[8] = 2.0f * C[1][3]; w[9] = 2.0f * C[2][3];
    #pragma unroll
    for (int i = 0; i < 4; i++) {
        float s = 0.0f;
        #pragma unroll
        for (int j = 0; j < 4; j++) s = fmaf(C[i][j], mu[j], s);
        w[10 + i] = -2.0f * s;
    }
    float q = 0.0f;
    #pragma unroll
    for (int i = 0; i < 4; i++) {
        float s = 0.0f;
        #pragma unroll
        for (int j = 0; j < 4; j++) s = fmaf(C[i][j], mu[j], s);
        q = fmaf(mu[i], s, q);
    }
    w[14] = q;
    w[15] = 0.0f;

    #pragma unroll
    for (int k = 0; k < 16; k++) w[k] = to_tf32(w[k]);

    const int t = m >> 3, j = m & 7;
    #pragma unroll
    for (int tg = 0; tg < 4; tg++) {
        g_tblB[t * 32 + 4 * j + tg] =
            make_float4(w[tg], w[tg + 4], w[tg + 8], w[tg + 12]);
    }

    // permuted label: round r = t>>1, odd = t&1, tg = j>>1, p = j&1
    {
        const int r = t >> 1, odd = t & 1, tg = j >> 1, p = j & 1;
        g_plab[r * 16 + tg * 4 + odd * 2 + p] = labels[m];
    }
}

// ---------------------------------------------------------------------------
// Decoder: 128 threads = 4 warps x 32 rays (two m16 row-groups per warp).
// Per round: 2 tiles x 2 k-steps x 2 ray-groups = 8 MMAs reusing one pair of
// B fragment loads -> LDS per ray-gaussian halved. Software-pipelined
// epilogue (16 ex2 + 16 FMA for round r-1 overlaps round r's MMAs).
// PDL launch: ray staging overlaps prep tail.
// ---------------------------------------------------------------------------
#define SM_TBL   0
#define SM_LAB   (NTILES * 32 * 16)                 // 65536
#define SM_STAGE (SM_LAB + M_G * 4)                 // 69632
#define STAGE_W  17
#define SM_TOTAL (SM_STAGE + RAYS_PER_BLOCK * STAGE_W * 4)  // 78336

extern __shared__ unsigned char smem_raw[];

__device__ __forceinline__ void mma_tf32(float& c0, float& c1, float& c2, float& c3,
                                         u32 a0, u32 a1, u32 a2, u32 a3,
                                         u32 b0, u32 b1) {
    asm volatile(
        "mma.sync.aligned.m16n8k8.row.col.f32.tf32.tf32.f32 "
        "{%0,%1,%2,%3}, {%4,%5,%6,%7}, {%8,%9}, {%0,%1,%2,%3};"
        : "+f"(c0), "+f"(c1), "+f"(c2), "+f"(c3)
        : "r"(a0), "r"(a1), "r"(a2), "r"(a3), "r"(b0), "r"(b1));
}

// 8 MMAs of one round: 2 tiles (bX,bY) x 2 ray-groups (g=0/1), K=16.
#define ROUND_MMAS(cXA, cYA, cXB, cYB)                                          \
    mma_tf32(cXA[0], cXA[1], cXA[2], cXA[3],                                    \
             afr[0][0][0], afr[0][0][1], afr[0][0][2], afr[0][0][3],            \
             __float_as_uint(bX.x), __float_as_uint(bX.y));                     \
    mma_tf32(cXA[0], cXA[1], cXA[2], cXA[3],                                    \
             afr[1][0][0], afr[1][0][1], afr[1][0][2], afr[1][0][3],            \
             __float_as_uint(bX.z), __float_as_uint(bX.w));                     \
    mma_tf32(cXB[0], cXB[1], cXB[2], cXB[3],                                    \
             afr[0][1][0], afr[0][1][1], afr[0][1][2], afr[0][1][3],            \
             __float_as_uint(bX.x), __float_as_uint(bX.y));                     \
    mma_tf32(cXB[0], cXB[1], cXB[2], cXB[3],                                    \
             afr[1][1][0], afr[1][1][1], afr[1][1][2], afr[1][1][3],            \
             __float_as_uint(bX.z), __float_as_uint(bX.w));                     \
    mma_tf32(cYA[0], cYA[1], cYA[2], cYA[3],                                    \
             afr[0][0][0], afr[0][0][1], afr[0][0][2], afr[0][0][3],            \
             __float_as_uint(bY.x), __float_as_uint(bY.y));                     \
    mma_tf32(cYA[0], cYA[1], cYA[2], cYA[3],                                    \
             afr[1][0][0], afr[1][0][1], afr[1][0][2], afr[1][0][3],            \
             __float_as_uint(bY.z), __float_as_uint(bY.w));                     \
    mma_tf32(cYB[0], cYB[1], cYB[2], cYB[3],                                    \
             afr[0][1][0], afr[0][1][1], afr[0][1][2], afr[0][1][3],            \
             __float_as_uint(bY.x), __float_as_uint(bY.y));                     \
    mma_tf32(cYB[0], cYB[1], cYB[2], cYB[3],                                    \
             afr[1][1][0], afr[1][1][1], afr[1][1][2], afr[1][1][3],            \
             __float_as_uint(bY.z), __float_as_uint(bY.w));

#define EPI8(P, La, Lb, aA, aB, aC, aD)                                         \
    {                                                                           \
        float e;                                                                \
        asm("ex2.approx.ftz.f32 %0, %1;" : "=f"(e) : "f"((P)[0]));              \
        aA = fmaf(La, e, aA);                                                   \
        asm("ex2.approx.ftz.f32 %0, %1;" : "=f"(e) : "f"((P)[1]));              \
        aB = fmaf(Lb, e, aB);                                                   \
        asm("ex2.approx.ftz.f32 %0, %1;" : "=f"(e) : "f"((P)[2]));              \
        aC = fmaf(La, e, aC);                                                   \
        asm("ex2.approx.ftz.f32 %0, %1;" : "=f"(e) : "f"((P)[3]));              \
        aD = fmaf(Lb, e, aD);                                                   \
    }

__global__ void __launch_bounds__(128, 2)
decoder_kernel(const float* __restrict__ origins,
               const float* __restrict__ dirs,
               float* __restrict__ out) {
    const int tid  = threadIdx.x;
    const int wid  = tid >> 5;
    const int lane = tid & 31;
    const int gid  = lane >> 2;   // row group 0..7
    const int tig  = lane & 3;    // thread-in-group

    // ---- A staging FIRST (independent of prep -> overlaps it under PDL) ----
    u32* stage = reinterpret_cast<u32*>(smem_raw + SM_STAGE) +
                 wid * RAYS_PER_WARP * STAGE_W;
    const int ray_base = blockIdx.x * RAYS_PER_BLOCK + wid * RAYS_PER_WARP;
    {
        const int n = ray_base + lane;   // every lane stages one ray
        const float2 o = reinterpret_cast<const float2*>(origins)[n];
        const float2 d = reinterpret_cast<const float2*>(dirs)[n];
        const float p0 = o.x, p1 = o.y, p2 = d.x, p3 = d.y;
        float phi[16];
        phi[0] = p0 * p0; phi[1] = p1 * p1; phi[2] = p2 * p2; phi[3] = p3 * p3;
        phi[4] = p0 * p1; phi[5] = p0 * p2; phi[6] = p0 * p3;
        phi[7] = p1 * p2; phi[8] = p1 * p3; phi[9] = p2 * p3;
        phi[10] = p0; phi[11] = p1; phi[12] = p2; phi[13] = p3;
        phi[14] = 1.0f; phi[15] = 0.0f;
        u32* row = stage + lane * STAGE_W;
        #pragma unroll
        for (int k = 0; k < 16; k++)
            row[k] = __float_as_uint(to_tf32(phi[k]));
    }

    // ---- PDL: wait for prep grid before touching its outputs ----
    asm volatile("griddepcontrol.wait;" ::: "memory");

    // ---- cooperative copies: B table (64KB) + permuted labels (4KB) ----
    {
        const uint4* gt = reinterpret_cast<const uint4*>(g_tblB);
        uint4* st = reinterpret_cast<uint4*>(smem_raw + SM_TBL);
        #pragma unroll
        for (int i = 0; i < (NTILES * 32 * 16 / 16) / 128; i++)
            st[tid + i * 128] = gt[tid + i * 128];
        const uint4* gl = reinterpret_cast<const uint4*>(g_plab);
        uint4* sl = reinterpret_cast<uint4*>(smem_raw + SM_LAB);
        sl[tid] = gl[tid];
        sl[tid + 128] = gl[tid + 128];
    }
    __syncthreads();

    // ---- load A fragments: [kstep][ray-group][frag] ----
    u32 afr[2][2][4];
    #pragma unroll
    for (int s = 0; s < 2; s++)
        #pragma unroll
        for (int g = 0; g < 2; g++) {
            const int r0 = g * 16 + gid, r1 = g * 16 + gid + 8;
            afr[s][g][0] = stage[r0 * STAGE_W + 8 * s + tig];
            afr[s][g][1] = stage[r1 * STAGE_W + 8 * s + tig];
            afr[s][g][2] = stage[r0 * STAGE_W + 8 * s + tig + 4];
            afr[s][g][3] = stage[r1 * STAGE_W + 8 * s + tig + 4];
        }

    const float4* tbl = reinterpret_cast<const float4*>(smem_raw + SM_TBL);
    const float4* lab4 = reinterpret_cast<const float4*>(smem_raw + SM_LAB);

    // accumulators: [group][lo/hi pair]
    float aA0 = 0.f, aA1 = 0.f, aA2 = 0.f, aA3 = 0.f;   // group 0
    float aB0 = 0.f, aB1 = 0.f, aB2 = 0.f, aB3 = 0.f;   // group 1

    // pipeline registers
    float pXA[4], pYA[4], pXB[4], pYB[4];
    float4 pL;

    // ---- prologue: round 0 ----
    {
        const float4 bX = tbl[lane];
        const float4 bY = tbl[32 + lane];
        pL = lab4[tig];
        float cXA[4] = {0,0,0,0}, cYA[4] = {0,0,0,0};
        float cXB[4] = {0,0,0,0}, cYB[4] = {0,0,0,0};
        ROUND_MMAS(cXA, cYA, cXB, cYB)
        #pragma unroll
        for (int k = 0; k < 4; k++) {
            pXA[k] = cXA[k]; pYA[k] = cYA[k];
            pXB[k] = cXB[k]; pYB[k] = cYB[k];
        }
    }

    // ---- pipelined main loop ----
    #pragma unroll 2
    for (int r = 1; r < NTILES / 2; r++) {
        const float4 bX = tbl[(2 * r)     * 32 + lane];
        const float4 bY = tbl[(2 * r + 1) * 32 + lane];
        const float4 L = lab4[r * 4 + tig];

        float cXA[4] = {0,0,0,0}, cYA[4] = {0,0,0,0};
        float cXB[4] = {0,0,0,0}, cYB[4] = {0,0,0,0};
        ROUND_MMAS(cXA, cYA, cXB, cYB)

        // epilogue of round r-1 overlaps in-flight MMAs
        EPI8(pXA, pL.x, pL.y, aA0, aA1, aA2, aA3)
        EPI8(pYA, pL.z, pL.w, aA0, aA1, aA2, aA3)
        EPI8(pXB, pL.x, pL.y, aB0, aB1, aB2, aB3)
        EPI8(pYB, pL.z, pL.w, aB0, aB1, aB2, aB3)

        #pragma unroll
        for (int k = 0; k < 4; k++) {
            pXA[k] = cXA[k]; pYA[k] = cYA[k];
            pXB[k] = cXB[k]; pYB[k] = cYB[k];
        }
        pL = L;
    }

    // ---- drain ----
    EPI8(pXA, pL.x, pL.y, aA0, aA1, aA2, aA3)
    EPI8(pYA, pL.z, pL.w, aA0, aA1, aA2, aA3)
    EPI8(pXB, pL.x, pL.y, aB0, aB1, aB2, aB3)
    EPI8(pYB, pL.z, pL.w, aB0, aB1, aB2, aB3)

    float sA_lo = aA0 + aA1, sA_hi = aA2 + aA3;   // rays gid, gid+8
    float sB_lo = aB0 + aB1, sB_hi = aB2 + aB3;   // rays 16+gid, 16+gid+8

    #pragma unroll
    for (int d = 1; d < 4; d <<= 1) {
        sA_lo += __shfl_xor_sync(0xffffffffu, sA_lo, d);
        sA_hi += __shfl_xor_sync(0xffffffffu, sA_hi, d);
        sB_lo += __shfl_xor_sync(0xffffffffu, sB_lo, d);
        sB_hi += __shfl_xor_sync(0xffffffffu, sB_hi, d);
    }

    if (tig == 0) {
        const float k = 1.4426950408889634f;
        float z, e, p;
        z = -sA_lo * k;
        asm("ex2.approx.ftz.f32 %0, %1;" : "=f"(e) : "f"(z));
        asm("rcp.approx.ftz.f32 %0, %1;" : "=f"(p) : "f"(1.0f + e));
        out[ray_base + gid] = p;
        z = -sA_hi * k;
        asm("ex2.approx.ftz.f32 %0, %1;" : "=f"(e) : "f"(z));
        asm("rcp.approx.ftz.f32 %0, %1;" : "=f"(p) : "f"(1.0f + e));
        out[ray_base + gid + 8] = p;
        z = -sB_lo * k;
        asm("ex2.approx.ftz.f32 %0, %1;" : "=f"(e) : "f"(z));
        asm("rcp.approx.ftz.f32 %0, %1;" : "=f"(p) : "f"(1.0f + e));
        out[ray_base + 16 + gid] = p;
        z = -sB_hi * k;
        asm("ex2.approx.ftz.f32 %0, %1;" : "=f"(e) : "f"(z));
        asm("rcp.approx.ftz.f32 %0, %1;" : "=f"(p) : "f"(1.0f + e));
        out[ray_base + 24 + gid] = p;
    }
}

// ---------------------------------------------------------------------------
extern "C" void kernel_launch(void* const* d_in, const int* in_sizes, int n_in,
                              void* d_out, int out_size) {
    const float* origins    = (const float*)d_in[0];
    const float* directions = (const float*)d_in[1];
    const float* means      = (const float*)d_in[2];
    const float* covs       = (const float*)d_in[3];
    const float* labels     = (const float*)d_in[4];
    float* out = (float*)d_out;

    prep_kernel<<<32, 32>>>(means, covs, labels);

    cudaFuncSetAttribute(decoder_kernel,
                         cudaFuncAttributeMaxDynamicSharedMemorySize, SM_TOTAL);

    cudaLaunchConfig_t cfg = {};
    cfg.gridDim  = dim3(N_RAYS / RAYS_PER_BLOCK, 1, 1);
    cfg.blockDim = dim3(128, 1, 1);
    cfg.dynamicSmemBytes = SM_TOTAL;
    cfg.stream = 0;
    cudaLaunchAttribute attrs[1];
    attrs[0].id = cudaLaunchAttributeProgrammaticStreamSerialization;
    attrs[0].val.programmaticStreamSerializationAllowed = 1;
    cfg.attrs = attrs;
    cfg.numAttrs = 1;
    cudaLaunchKernelEx(&cfg, decoder_kernel, origins, directions, out);
}